// round 2
// baseline (speedup 1.0000x reference)
#include <cuda_runtime.h>
#include <math.h>
#include <stdint.h>

#define BB   4
#define CIN  128
#define COUT 128
#define HH   128
#define WW   128
#define HW   (HH*WW)
#define KK   9

// ---------------- scratch (static device arrays: allowed) ----------------
__device__ float g_nhwc[BB*HW*CIN];      // inp transposed to [b][y][x][ci]  (33.5 MB)
__device__ float g_off [BB*HW*27];       // per pixel: py[9], px[9], mask[9] (7.1 MB)
__device__ float g_wt  [KK*CIN*COUT];    // w_dc transposed to [tap][ci][co] (0.6 MB)

// ---------------- f32x2 helpers ----------------
__device__ __forceinline__ void fma2(unsigned long long &d, unsigned long long a, unsigned long long b) {
    asm("fma.rn.f32x2 %0, %1, %2, %0;" : "+l"(d) : "l"(a), "l"(b));
}
__device__ __forceinline__ unsigned long long dup2(float x) {
    unsigned long long r;
    asm("mov.b64 %0, {%1, %1};" : "=l"(r) : "f"(x));
    return r;
}
__device__ __forceinline__ float2 unpk(unsigned long long v) {
    float2 r;
    asm("mov.b64 {%0, %1}, %2;" : "=f"(r.x), "=f"(r.y) : "l"(v));
    return r;
}

// ---------------- Kernel A: NCHW -> NHWC transpose of inp ----------------
__global__ void k_transpose(const float* __restrict__ inp) {
    __shared__ float tile[32][33];
    int b  = blockIdx.z;
    int c0 = blockIdx.y * 32;
    int p0 = blockIdx.x * 32;
    int tx = threadIdx.x, ty = threadIdx.y;
#pragma unroll
    for (int i = 0; i < 4; i++) {
        int c = c0 + ty + i * 8;
        tile[ty + i * 8][tx] = inp[(b * CIN + c) * HW + p0 + tx];
    }
    __syncthreads();
#pragma unroll
    for (int i = 0; i < 4; i++) {
        int p = p0 + ty + i * 8;
        g_nhwc[((size_t)b * HW + p) * CIN + c0 + tx] = tile[tx][ty + i * 8];
    }
}

// ---------------- Kernel E: w_dc [co][ci][9] -> g_wt [tap][ci][co] ----------------
__global__ void k_wt(const float* __restrict__ w_dc) {
    int idx = blockIdx.x * blockDim.x + threadIdx.x;
    if (idx >= KK * CIN * COUT) return;
    int t  = idx / (CIN * COUT);
    int r  = idx % (CIN * COUT);
    int ci = r / COUT;
    int co = r % COUT;
    g_wt[idx] = w_dc[(co * CIN + ci) * KK + t];
}

// ---------------- Kernel B: offset conv (27 ch) + transform ----------------
// one block per (b, y); 128 threads, one per x.
__global__ __launch_bounds__(128) void k_offset(const float* __restrict__ feat,
                                                const float* __restrict__ w_off,
                                                const float* __restrict__ b_off) {
    __shared__ float shf[8 * 3 * 130];   // [ci][ky][j], j = x+1 (halo)
    __shared__ float sw [27 * 72];       // [oc][ci*9+kk]
    int b = blockIdx.x >> 7;
    int y = blockIdx.x & 127;
    int x = threadIdx.x;
    float acc[27];
#pragma unroll
    for (int i = 0; i < 27; i++) acc[i] = 0.f;

    for (int cc = 0; cc < CIN / 8; cc++) {
        __syncthreads();
        // stage feat rows (3 rows, 8 channels, halo cols)
        for (int e = threadIdx.x; e < 3120; e += 128) {
            int ci = e / 390;
            int r  = e % 390;
            int ky = r / 130;
            int j  = r % 130;
            int yy = y + ky - 1;
            int xx = j - 1;
            float v = 0.f;
            if (yy >= 0 && yy < HH && xx >= 0 && xx < WW)
                v = feat[((b * CIN + cc * 8 + ci) * HH + yy) * WW + xx];
            shf[e] = v;
        }
        // stage weights
        for (int e = threadIdx.x; e < 1944; e += 128) {
            int oc = e / 72;
            int r  = e % 72;               // ci*9 + kk
            sw[e] = w_off[(oc * CIN + cc * 8 + r / 9) * KK + (r % 9)];
        }
        __syncthreads();
#pragma unroll
        for (int ci = 0; ci < 8; ci++) {
#pragma unroll
            for (int ky = 0; ky < 3; ky++) {
                const float v0 = shf[(ci * 3 + ky) * 130 + x];
                const float v1 = shf[(ci * 3 + ky) * 130 + x + 1];
                const float v2 = shf[(ci * 3 + ky) * 130 + x + 2];
                const float* wrow = &sw[ci * 9 + ky * 3];
#pragma unroll
                for (int oc = 0; oc < 27; oc++) {
                    acc[oc] += v0 * wrow[oc * 72 + 0]
                             + v1 * wrow[oc * 72 + 1]
                             + v2 * wrow[oc * 72 + 2];
                }
            }
        }
    }
#pragma unroll
    for (int oc = 0; oc < 27; oc++) acc[oc] += b_off[oc];

    // transform -> py, px, mask
    int   pix  = (b * HH + y) * WW + x;
    float* o   = &g_off[(size_t)pix * 27];
#pragma unroll
    for (int k = 0; k < 9; k++) {
        int ky = k / 3, kx = k % 3;
        float py = acc[2 * k]     + (float)(y + ky - 1);
        float px = acc[2 * k + 1] + (float)(x + kx - 1);
        float m  = 1.f / (1.f + __expf(-acc[18 + k]));
        o[k]      = py;
        o[9 + k]  = px;
        o[18 + k] = m;
    }
}

// ---------------- Kernel C: fused bilinear-sample + deform GEMM ----------------
// one block per (b, y): 128 pixels, 128 cout. 512 threads.
// smem: s[128ci][pitch 132] sampled tile  +  w[128ci][128co] for current tap.
#define SPITCH 132
#define SMEM_S_FLOATS (CIN * SPITCH)
#define SMEM_W_FLOATS (CIN * COUT)
#define SMEM_C_BYTES  ((SMEM_S_FLOATS + SMEM_W_FLOATS) * 4)

__global__ __launch_bounds__(512, 1) void k_main(const float* __restrict__ b_dc,
                                                 float* __restrict__ out) {
    extern __shared__ float smem[];
    float* s_s = smem;                       // sampled [ci][px]
    float* s_w = smem + SMEM_S_FLOATS;       // weights [ci][co]

    const int tid  = threadIdx.x;
    const int b    = blockIdx.x >> 7;
    const int y    = blockIdx.x & 127;
    const int lane = tid & 31;
    const int warp = tid >> 5;
    const int co0  = warp * 8;
    const int p0   = lane * 4;

    // sampling roles
    const int sp = tid >> 2;      // pixel x (0..127)
    const int cg = tid & 3;       // ci group (32 each)
    const int ci0 = cg * 32;

    const float* ofs    = &g_off[((size_t)(b * HH + y) * WW + sp) * 27];
    const float* base_b = g_nhwc + (size_t)b * HW * CIN;

    unsigned long long acc[16];
#pragma unroll
    for (int i = 0; i < 16; i++) acc[i] = 0ULL;

    for (int t = 0; t < KK; t++) {
        __syncthreads();   // previous GEMM done with smem

        // stage weights for this tap (coalesced float4)
        {
            const float4* src = (const float4*)(g_wt + (size_t)t * CIN * COUT);
            float4* dst = (float4*)s_w;
            for (int e = tid; e < (CIN * COUT) / 4; e += 512) dst[e] = src[e];
        }

        // bilinear sampling into s_s
        {
            float py = ofs[t];
            float px = ofs[9 + t];
            float m  = ofs[18 + t];
            float y0f = floorf(py), x0f = floorf(px);
            float ly = py - y0f, lx = px - x0f;
            int y0 = (int)y0f, x0 = (int)x0f;
            int y1 = y0 + 1,   x1 = x0 + 1;
            float f00 = (y0 >= 0 && y0 < HH && x0 >= 0 && x0 < WW) ? 1.f : 0.f;
            float f01 = (y0 >= 0 && y0 < HH && x1 >= 0 && x1 < WW) ? 1.f : 0.f;
            float f10 = (y1 >= 0 && y1 < HH && x0 >= 0 && x0 < WW) ? 1.f : 0.f;
            float f11 = (y1 >= 0 && y1 < HH && x1 >= 0 && x1 < WW) ? 1.f : 0.f;
            float w00 = (1.f - ly) * (1.f - lx) * m * f00;
            float w01 = (1.f - ly) * lx         * m * f01;
            float w10 = ly         * (1.f - lx) * m * f10;
            float w11 = ly         * lx         * m * f11;
            int y0c = min(max(y0, 0), HH - 1), x0c = min(max(x0, 0), WW - 1);
            int y1c = min(max(y1, 0), HH - 1), x1c = min(max(x1, 0), WW - 1);
            const float* r00 = base_b + ((size_t)(y0c * WW + x0c)) * CIN;
            const float* r01 = base_b + ((size_t)(y0c * WW + x1c)) * CIN;
            const float* r10 = base_b + ((size_t)(y1c * WW + x0c)) * CIN;
            const float* r11 = base_b + ((size_t)(y1c * WW + x1c)) * CIN;
#pragma unroll
            for (int i = 0; i < 8; i++) {
                int ci = ci0 + i * 4;
                float4 a = *(const float4*)(r00 + ci);
                float4 c = *(const float4*)(r01 + ci);
                float4 d = *(const float4*)(r10 + ci);
                float4 e = *(const float4*)(r11 + ci);
                s_s[(ci + 0) * SPITCH + sp] = w00 * a.x + w01 * c.x + w10 * d.x + w11 * e.x;
                s_s[(ci + 1) * SPITCH + sp] = w00 * a.y + w01 * c.y + w10 * d.y + w11 * e.y;
                s_s[(ci + 2) * SPITCH + sp] = w00 * a.z + w01 * c.z + w10 * d.z + w11 * e.z;
                s_s[(ci + 3) * SPITCH + sp] = w00 * a.w + w01 * c.w + w10 * d.w + w11 * e.w;
            }
        }
        __syncthreads();

        // GEMM: acc[8co x 4px] += w[ci][co-pairs] * s[ci][px]
#pragma unroll 4
        for (int ci = 0; ci < CIN; ci++) {
            const float4 sv = *(const float4*)(s_s + ci * SPITCH + p0);
            const ulonglong2 wA = *(const ulonglong2*)(s_w + ci * COUT + co0);
            const ulonglong2 wB = *(const ulonglong2*)(s_w + ci * COUT + co0 + 4);
            unsigned long long q0 = dup2(sv.x);
            unsigned long long q1 = dup2(sv.y);
            unsigned long long q2 = dup2(sv.z);
            unsigned long long q3 = dup2(sv.w);
            fma2(acc[0],  wA.x, q0); fma2(acc[1],  wA.x, q1); fma2(acc[2],  wA.x, q2); fma2(acc[3],  wA.x, q3);
            fma2(acc[4],  wA.y, q0); fma2(acc[5],  wA.y, q1); fma2(acc[6],  wA.y, q2); fma2(acc[7],  wA.y, q3);
            fma2(acc[8],  wB.x, q0); fma2(acc[9],  wB.x, q1); fma2(acc[10], wB.x, q2); fma2(acc[11], wB.x, q3);
            fma2(acc[12], wB.y, q0); fma2(acc[13], wB.y, q1); fma2(acc[14], wB.y, q2); fma2(acc[15], wB.y, q3);
        }
    }

    // epilogue: unpack, add bias, store NCHW (coalesced float4 per co)
#pragma unroll
    for (int cp = 0; cp < 4; cp++) {
        float2 v0 = unpk(acc[cp * 4 + 0]);
        float2 v1 = unpk(acc[cp * 4 + 1]);
        float2 v2 = unpk(acc[cp * 4 + 2]);
        float2 v3 = unpk(acc[cp * 4 + 3]);
        int coA = co0 + 2 * cp;
        float bA = b_dc[coA];
        float bBv = b_dc[coA + 1];
        float4 ra = make_float4(v0.x + bA,  v1.x + bA,  v2.x + bA,  v3.x + bA);
        float4 rb = make_float4(v0.y + bBv, v1.y + bBv, v2.y + bBv, v3.y + bBv);
        *(float4*)(out + ((size_t)(b * COUT + coA)     * HH + y) * WW + p0) = ra;
        *(float4*)(out + ((size_t)(b * COUT + coA + 1) * HH + y) * WW + p0) = rb;
    }
}

// ---------------- launch ----------------
extern "C" void kernel_launch(void* const* d_in, const int* in_sizes, int n_in,
                              void* d_out, int out_size) {
    const float* inp   = (const float*)d_in[0];
    const float* feat  = (const float*)d_in[1];
    const float* w_off = (const float*)d_in[2];
    const float* b_off = (const float*)d_in[3];
    const float* w_dc  = (const float*)d_in[4];
    const float* b_dc  = (const float*)d_in[5];
    float* out = (float*)d_out;

    k_transpose<<<dim3(HW / 32, CIN / 32, BB), dim3(32, 8)>>>(inp);
    k_wt<<<(KK * CIN * COUT + 255) / 256, 256>>>(w_dc);
    k_offset<<<BB * HH, 128>>>(feat, w_off, b_off);

    static bool attr_set = false;
    if (!attr_set) {
        cudaFuncSetAttribute(k_main, cudaFuncAttributeMaxDynamicSharedMemorySize, SMEM_C_BYTES);
        attr_set = true;
    }
    k_main<<<BB * HH, 512, SMEM_C_BYTES>>>(b_dc, out);
}

// round 7
// speedup vs baseline: 1.5794x; 1.5794x over previous
#include <cuda_runtime.h>
#include <cuda_bf16.h>
#include <stdint.h>
#include <math.h>

#define BB   4
#define CIN  128
#define COUT 128
#define HH   128
#define WW   128
#define HW   (HH*WW)

// ---------------- global scratch ----------------
__device__ float g_nhwc[BB*HW*CIN];                       // inp NHWC
__device__ float g_off [BB*HW*27];                        // py[9], px[9], mask[9]
__device__ __align__(16) __nv_bfloat16 g_wtA[9*2*16384];  // per tap: swizzled [co][ci] hi tile + lo tile
__device__ __align__(16) float g_woff[1152*28];           // w_off transposed [ci][k][28oc]

// ---------------- f32x2 helpers ----------------
__device__ __forceinline__ void fma2(unsigned long long &d, unsigned long long a, unsigned long long b) {
    asm("fma.rn.f32x2 %0, %1, %2, %0;" : "+l"(d) : "l"(a), "l"(b));
}
__device__ __forceinline__ unsigned long long dup2(float x) {
    unsigned long long r; asm("mov.b64 %0, {%1, %1};" : "=l"(r) : "f"(x)); return r;
}
__device__ __forceinline__ float2 unpk(unsigned long long v) {
    float2 r; asm("mov.b64 {%0, %1}, %2;" : "=f"(r.x), "=f"(r.y) : "l"(v)); return r;
}

// ---------------- tensor-core helpers (baseline PTX, sm_80+) ----------------
__device__ __forceinline__ uint32_t smem_u32(const void* p) {
    uint32_t a;
    asm("{ .reg .u64 t; cvta.to.shared.u64 t, %1; cvt.u32.u64 %0, t; }" : "=r"(a) : "l"(p));
    return a;
}
__device__ __forceinline__ void ldmx4(uint32_t* r, uint32_t addr) {
    asm volatile("ldmatrix.sync.aligned.m8n8.x4.shared.b16 {%0,%1,%2,%3}, [%4];"
        : "=r"(r[0]), "=r"(r[1]), "=r"(r[2]), "=r"(r[3]) : "r"(addr));
}
__device__ __forceinline__ void mma_bf16(float* d, const uint32_t* a, const uint32_t* b) {
    asm volatile("mma.sync.aligned.m16n8k16.row.col.f32.bf16.bf16.f32 "
        "{%0,%1,%2,%3}, {%4,%5,%6,%7}, {%8,%9}, {%0,%1,%2,%3};"
        : "+f"(d[0]), "+f"(d[1]), "+f"(d[2]), "+f"(d[3])
        : "r"(a[0]), "r"(a[1]), "r"(a[2]), "r"(a[3]), "r"(b[0]), "r"(b[1]));
}

// swizzled byte offset in a [128 rows][128 cols-bf16] tile, pitch 256 B.
// chunk(16B) index XORed with (row&7): every ldmatrix 8-row phase hits 8 distinct bank groups.
__device__ __forceinline__ uint32_t tswz(int row, int ci) {
    return (uint32_t)(row * 256 + ((((ci >> 3) ^ (row & 7)) << 4) | ((ci & 7) * 2)));
}

// ---------------- Kernel: NCHW -> NHWC transpose of inp ----------------
__global__ void k_transpose(const float* __restrict__ inp) {
    __shared__ float tile[32][33];
    int b = blockIdx.z, c0 = blockIdx.y * 32, p0 = blockIdx.x * 32;
    int tx = threadIdx.x, ty = threadIdx.y;
#pragma unroll
    for (int i = 0; i < 4; i++)
        tile[ty + i * 8][tx] = inp[(b * CIN + c0 + ty + i * 8) * HW + p0 + tx];
    __syncthreads();
#pragma unroll
    for (int i = 0; i < 4; i++)
        g_nhwc[((size_t)b * HW + p0 + ty + i * 8) * CIN + c0 + tx] = tile[tx][ty + i * 8];
}

// ---------------- Kernel: w_dc -> swizzled bf16 hi/lo A tiles [co][ci] ----------------
__global__ void k_prep_wtA(const float* __restrict__ w_dc) {
    int idx = blockIdx.x * blockDim.x + threadIdx.x;
    if (idx >= 9 * 16384) return;
    int t  = idx >> 14;
    int r  = idx & 16383;
    int co = r >> 7;
    int ci = r & 127;
    float w = w_dc[(co * CIN + ci) * 9 + t];
    __nv_bfloat16 h = __float2bfloat16(w);
    __nv_bfloat16 l = __float2bfloat16(w - __bfloat162float(h));
    uint32_t e = tswz(co, ci) >> 1;
    g_wtA[t * 32768 + e]         = h;
    g_wtA[t * 32768 + 16384 + e] = l;
}

// ---------------- Kernel: w_off -> [ci][k][28] ----------------
__global__ void k_prep_woff(const float* __restrict__ w_off) {
    int idx = blockIdx.x * blockDim.x + threadIdx.x;
    if (idx >= 1152 * 28) return;
    int row = idx / 28, j = idx % 28;
    int ci = row / 9, k = row % 9;
    g_woff[idx] = (j < 27) ? w_off[(j * CIN + ci) * 9 + k] : 0.f;
}

// ---------------- Kernel: offset conv (f32x2, vector weights) ----------------
__global__ __launch_bounds__(128) void k_offset(const float* __restrict__ feat,
                                                const float* __restrict__ b_off) {
    __shared__ __align__(16) float shf[3120];   // [8ci][3ky][130]
    __shared__ __align__(16) float sw [2016];   // [8ci][9k][28oc]
    int b = blockIdx.x >> 7, y = blockIdx.x & 127, x = threadIdx.x;
    unsigned long long acc2[14];
#pragma unroll
    for (int i = 0; i < 14; i++) acc2[i] = 0ULL;

    for (int cc = 0; cc < 16; cc++) {
        __syncthreads();
        for (int e = x; e < 3120; e += 128) {
            int ci = e / 390; int r = e - ci * 390;
            int ky = r / 130; int j = r - ky * 130;
            int yy = y + ky - 1, xx = j - 1;
            float v = 0.f;
            if (yy >= 0 && yy < HH && xx >= 0 && xx < WW)
                v = feat[((b * CIN + cc * 8 + ci) * HH + yy) * WW + xx];
            shf[e] = v;
        }
        for (int e = x; e < 2016; e += 128) sw[e] = g_woff[cc * 2016 + e];
        __syncthreads();
        const ulonglong2* wp = (const ulonglong2*)sw;
#pragma unroll
        for (int ci = 0; ci < 8; ci++) {
#pragma unroll
            for (int ky = 0; ky < 3; ky++) {
                float vv[3];
                vv[0] = shf[(ci * 3 + ky) * 130 + x];
                vv[1] = shf[(ci * 3 + ky) * 130 + x + 1];
                vv[2] = shf[(ci * 3 + ky) * 130 + x + 2];
#pragma unroll
                for (int kx = 0; kx < 3; kx++) {
                    unsigned long long vd = dup2(vv[kx]);
                    const ulonglong2* w = wp + (ci * 9 + ky * 3 + kx) * 7;
#pragma unroll
                    for (int j = 0; j < 7; j++) {
                        ulonglong2 ww = w[j];
                        fma2(acc2[2 * j],     ww.x, vd);
                        fma2(acc2[2 * j + 1], ww.y, vd);
                    }
                }
            }
        }
    }
    float accf[28];
#pragma unroll
    for (int i = 0; i < 14; i++) { float2 u = unpk(acc2[i]); accf[2 * i] = u.x; accf[2 * i + 1] = u.y; }
#pragma unroll
    for (int oc = 0; oc < 27; oc++) accf[oc] += b_off[oc];

    float* o = &g_off[((size_t)(b * HH + y) * WW + x) * 27];
#pragma unroll
    for (int k = 0; k < 9; k++) {
        int ky = k / 3, kx = k % 3;
        o[k]      = accf[2 * k]     + (float)(y + ky - 1);
        o[9 + k]  = accf[2 * k + 1] + (float)(x + kx - 1);
        o[18 + k] = 1.f / (1.f + __expf(-accf[18 + k]));
    }
}

// ---------------- Kernel: mma.sync bf16-split deform GEMM ----------------
// one block per (b,y): 128 cout x 128 px, K = 128ci x 9 taps, 3-term bf16 split.
// smem: A_hi 32K | A_lo 32K | S_hi 32K | S_lo 32K  = 128 KB
#define OFF_A   0
#define OFF_B   65536
#define SMEM_BYTES 131072

__global__ __launch_bounds__(512) void k_main(const float* __restrict__ b_dc,
                                              float* __restrict__ out) {
    extern __shared__ __align__(1024) char smem[];
    const uint32_t sbase = smem_u32(smem);
    const int tid = threadIdx.x, lane = tid & 31, warp = tid >> 5;
    const int b = blockIdx.x >> 7, y = blockIdx.x & 127;

    // GEMM roles: 4x4 warp grid; warp tile = 32co x 32px
    const int mrow = (warp & 3) * 32;
    const int ncol = (warp >> 2) * 32;
    const int sub = lane >> 3, lr = lane & 7;
    const uint32_t aoff0 = (uint32_t)(mrow + (sub & 1) * 8 + lr) * 256;
    const uint32_t aoff1 = aoff0 + 16 * 256;
    const int kxa = sub >> 1;
    const uint32_t boff0 = (uint32_t)(ncol + (sub >> 1) * 8 + lr) * 256;
    const uint32_t boff1 = boff0 + 16 * 256;
    const int kxb = sub & 1;
    const uint32_t sAh = sbase + OFF_A, sAl = sAh + 32768;
    const uint32_t sBh = sbase + OFF_B, sBl = sBh + 32768;

    // sampling roles
    const int sp  = tid >> 2;          // pixel x
    const int ci0 = (tid & 3) * 32;    // ci group
    const float* ofs    = &g_off[((size_t)(b * HH + y) * WW + sp) * 27];
    const float* base_b = g_nhwc + (size_t)b * HW * CIN;

    float acc[2][4][4];
#pragma unroll
    for (int i = 0; i < 2; i++)
#pragma unroll
        for (int j = 0; j < 4; j++)
#pragma unroll
            for (int k = 0; k < 4; k++) acc[i][j][k] = 0.f;

    for (int t = 0; t < 9; t++) {
        __syncthreads();   // previous GEMM done reading smem

        // stage A hi+lo (64 KB linear copy, pre-swizzled in global)
        {
            const float4* src = (const float4*)(g_wtA + (size_t)t * 32768);
            float4* dst = (float4*)(smem + OFF_A);
#pragma unroll
            for (int e = 0; e < 8; e++) dst[tid + e * 512] = src[tid + e * 512];
        }
        // bilinear sample -> bf16 hi/lo S tiles [px][ci] (swizzled)
        {
            float py = ofs[t], pxx = ofs[9 + t], m = ofs[18 + t];
            float y0f = floorf(py), x0f = floorf(pxx);
            float ly = py - y0f, lx = pxx - x0f;
            int y0 = (int)y0f, x0 = (int)x0f, y1 = y0 + 1, x1 = x0 + 1;
            float f00 = (y0 >= 0 && y0 < HH && x0 >= 0 && x0 < WW) ? 1.f : 0.f;
            float f01 = (y0 >= 0 && y0 < HH && x1 >= 0 && x1 < WW) ? 1.f : 0.f;
            float f10 = (y1 >= 0 && y1 < HH && x0 >= 0 && x0 < WW) ? 1.f : 0.f;
            float f11 = (y1 >= 0 && y1 < HH && x1 >= 0 && x1 < WW) ? 1.f : 0.f;
            float w00 = (1.f - ly) * (1.f - lx) * m * f00;
            float w01 = (1.f - ly) * lx         * m * f01;
            float w10 = ly         * (1.f - lx) * m * f10;
            float w11 = ly         * lx         * m * f11;
            int y0c = min(max(y0, 0), HH - 1), x0c = min(max(x0, 0), WW - 1);
            int y1c = min(max(y1, 0), HH - 1), x1c = min(max(x1, 0), WW - 1);
            const float* r00 = base_b + ((size_t)(y0c * WW + x0c)) * CIN;
            const float* r01 = base_b + ((size_t)(y0c * WW + x1c)) * CIN;
            const float* r10 = base_b + ((size_t)(y1c * WW + x0c)) * CIN;
            const float* r11 = base_b + ((size_t)(y1c * WW + x1c)) * CIN;
#pragma unroll
            for (int i = 0; i < 8; i++) {
                int ci = ci0 + i * 4;
                float4 a = *(const float4*)(r00 + ci);
                float4 c = *(const float4*)(r01 + ci);
                float4 d = *(const float4*)(r10 + ci);
                float4 e = *(const float4*)(r11 + ci);
                float v0 = w00 * a.x + w01 * c.x + w10 * d.x + w11 * e.x;
                float v1 = w00 * a.y + w01 * c.y + w10 * d.y + w11 * e.y;
                float v2 = w00 * a.z + w01 * c.z + w10 * d.z + w11 * e.z;
                float v3 = w00 * a.w + w01 * c.w + w10 * d.w + w11 * e.w;
                __nv_bfloat16 h0 = __float2bfloat16(v0);
                __nv_bfloat16 h1 = __float2bfloat16(v1);
                __nv_bfloat16 h2 = __float2bfloat16(v2);
                __nv_bfloat16 h3 = __float2bfloat16(v3);
                __nv_bfloat16 l0 = __float2bfloat16(v0 - __bfloat162float(h0));
                __nv_bfloat16 l1 = __float2bfloat16(v1 - __bfloat162float(h1));
                __nv_bfloat16 l2 = __float2bfloat16(v2 - __bfloat162float(h2));
                __nv_bfloat16 l3 = __float2bfloat16(v3 - __bfloat162float(h3));
                uint32_t hi01 = ((uint32_t)__bfloat16_as_ushort(h1) << 16) | __bfloat16_as_ushort(h0);
                uint32_t hi23 = ((uint32_t)__bfloat16_as_ushort(h3) << 16) | __bfloat16_as_ushort(h2);
                uint32_t lo01 = ((uint32_t)__bfloat16_as_ushort(l1) << 16) | __bfloat16_as_ushort(l0);
                uint32_t lo23 = ((uint32_t)__bfloat16_as_ushort(l3) << 16) | __bfloat16_as_ushort(l2);
                uint32_t a0 = tswz(sp, ci);   // 8B-aligned, 4 ci within one 16B chunk
                *(unsigned long long*)(smem + OFF_B + a0)         = ((unsigned long long)hi23 << 32) | hi01;
                *(unsigned long long*)(smem + OFF_B + 32768 + a0) = ((unsigned long long)lo23 << 32) | lo01;
            }
        }
        __syncthreads();

        // GEMM: 8 k-steps, 3 split terms, 2x4 mma tiles per warp
#pragma unroll
        for (int ks = 0; ks < 8; ks++) {
            uint32_t ca = (uint32_t)(((2 * ks + kxa) ^ lr) << 4);
            uint32_t cb = (uint32_t)(((2 * ks + kxb) ^ lr) << 4);
            uint32_t ah0[4], ah1[4], al0[4], al1[4];
            ldmx4(ah0, sAh + aoff0 + ca);
            ldmx4(ah1, sAh + aoff1 + ca);
            ldmx4(al0, sAl + aoff0 + ca);
            ldmx4(al1, sAl + aoff1 + ca);
            uint32_t bh[4][2], bl[4][2], q[4];
            ldmx4(q, sBh + boff0 + cb); bh[0][0]=q[0]; bh[0][1]=q[1]; bh[1][0]=q[2]; bh[1][1]=q[3];
            ldmx4(q, sBh + boff1 + cb); bh[2][0]=q[0]; bh[2][1]=q[1]; bh[3][0]=q[2]; bh[3][1]=q[3];
            ldmx4(q, sBl + boff0 + cb); bl[0][0]=q[0]; bl[0][1]=q[1]; bl[1][0]=q[2]; bl[1][1]=q[3];
            ldmx4(q, sBl + boff1 + cb); bl[2][0]=q[0]; bl[2][1]=q[1]; bl[3][0]=q[2]; bl[3][1]=q[3];
#pragma unroll
            for (int nt = 0; nt < 4; nt++) {
                mma_bf16(acc[0][nt], ah0, bh[nt]);
                mma_bf16(acc[1][nt], ah1, bh[nt]);
                mma_bf16(acc[0][nt], al0, bh[nt]);
                mma_bf16(acc[1][nt], al1, bh[nt]);
                mma_bf16(acc[0][nt], ah0, bl[nt]);
                mma_bf16(acc[1][nt], ah1, bl[nt]);
            }
        }
    }

    // epilogue: d-frag -> gmem NCHW with bias (8B stores, 32B-sector aligned groups)
    const int g = lane >> 2, tig = lane & 3;
#pragma unroll
    for (int mt = 0; mt < 2; mt++) {
        int coA = mrow + mt * 16 + g;
        int coB = coA + 8;
        float bA = b_dc[coA], bB2 = b_dc[coB];
        float* oA = out + ((size_t)(b * COUT + coA) * HH + y) * WW;
        float* oB = out + ((size_t)(b * COUT + coB) * HH + y) * WW;
#pragma unroll
        for (int nt = 0; nt < 4; nt++) {
            int px = ncol + nt * 8 + 2 * tig;
            float2 vA = make_float2(acc[mt][nt][0] + bA,  acc[mt][nt][1] + bA);
            float2 vB = make_float2(acc[mt][nt][2] + bB2, acc[mt][nt][3] + bB2);
            *(float2*)(oA + px) = vA;
            *(float2*)(oB + px) = vB;
        }
    }
}

// ---------------- launch ----------------
extern "C" void kernel_launch(void* const* d_in, const int* in_sizes, int n_in,
                              void* d_out, int out_size) {
    const float* inp   = (const float*)d_in[0];
    const float* feat  = (const float*)d_in[1];
    const float* w_off = (const float*)d_in[2];
    const float* b_off = (const float*)d_in[3];
    const float* w_dc  = (const float*)d_in[4];
    const float* b_dc  = (const float*)d_in[5];
    float* out = (float*)d_out;

    static bool attr_set = false;
    if (!attr_set) {
        cudaFuncSetAttribute(k_main, cudaFuncAttributeMaxDynamicSharedMemorySize, SMEM_BYTES);
        attr_set = true;
    }

    k_transpose<<<dim3(HW / 32, CIN / 32, BB), dim3(32, 8)>>>(inp);
    k_prep_wtA<<<(9 * 16384 + 255) / 256, 256>>>(w_dc);
    k_prep_woff<<<(1152 * 28 + 255) / 256, 256>>>(w_off);
    k_offset<<<BB * HH, 128>>>(feat, b_off);
    k_main<<<BB * HH, 512, SMEM_BYTES>>>(b_dc, out);
}